// round 5
// baseline (speedup 1.0000x reference)
#include <cuda_runtime.h>

#define BB   2
#define NN   8192
#define KK   16
#define CIN  64
#define COUT 128
#define NPTS (BB * NN)

// Scratch for projected q/k/v (device globals: no allocation allowed in kernel_launch)
__device__ float g_q[NPTS * COUT];
__device__ float g_k[NPTS * COUT];
__device__ float g_v[NPTS * COUT];

// ---------------------------------------------------------------------------
// Kernel 1: q = x@Wq+bq ; k,v = x@Wkv+bkv  (split into 3 col-groups of 128)
// Block: 16 rows x 128 cols, 128 threads, each thread a 4x4 register tile.
// ---------------------------------------------------------------------------
__global__ void __launch_bounds__(128) proj_kernel(
    const float* __restrict__ x,
    const float* __restrict__ Wq,  const float* __restrict__ bq,
    const float* __restrict__ Wkv, const float* __restrict__ bkv)
{
    __shared__ float s_x[16][64];

    const int tid  = threadIdx.x;
    const int row0 = blockIdx.x * 16;
    const int g    = blockIdx.y;

    // load 16x64 x-tile (256 float4 by 128 threads)
    for (int i = tid; i < 256; i += 128) {
        int r = i >> 4, c4 = i & 15;
        reinterpret_cast<float4*>(&s_x[r][0])[c4] =
            reinterpret_cast<const float4*>(x + (size_t)(row0 + r) * CIN)[c4];
    }
    __syncthreads();

    const int rt = tid >> 5;   // row tile: rows rt*4 .. rt*4+3
    const int l  = tid & 31;   // col tile: cols 4l .. 4l+3

    const float* W;
    const float* bias;
    float*       out;
    int ldw, cb;
    if (g == 0)      { W = Wq;  ldw = 128; cb = 0;   bias = bq;        out = g_q; }
    else if (g == 1) { W = Wkv; ldw = 256; cb = 0;   bias = bkv;       out = g_k; }
    else             { W = Wkv; ldw = 256; cb = 128; bias = bkv + 128; out = g_v; }

    float4 acc[4];
    #pragma unroll
    for (int r = 0; r < 4; ++r) acc[r] = make_float4(0.f, 0.f, 0.f, 0.f);

    const float* wp = W + cb + 4 * l;
    #pragma unroll 4
    for (int k = 0; k < CIN; ++k) {
        float4 w = *reinterpret_cast<const float4*>(wp + (size_t)k * ldw);
        #pragma unroll
        for (int r = 0; r < 4; ++r) {
            float a = s_x[rt * 4 + r][k];
            acc[r].x = fmaf(a, w.x, acc[r].x);
            acc[r].y = fmaf(a, w.y, acc[r].y);
            acc[r].z = fmaf(a, w.z, acc[r].z);
            acc[r].w = fmaf(a, w.w, acc[r].w);
        }
    }

    float4 bv = *reinterpret_cast<const float4*>(bias + 4 * l);
    #pragma unroll
    for (int r = 0; r < 4; ++r) {
        float4 o = acc[r];
        o.x += bv.x; o.y += bv.y; o.z += bv.z; o.w += bv.w;
        *reinterpret_cast<float4*>(out + (size_t)(row0 + rt * 4 + r) * COUT + 4 * l) = o;
    }
}

// ---------------------------------------------------------------------------
// Register-tiled 16x128 @ 128x128 GEMM stage (sIn in smem, W in L1-cached gmem)
// ---------------------------------------------------------------------------
__device__ __forceinline__ void gemm16x128(
    const float* __restrict__ sIn, const float* __restrict__ W,
    const float* __restrict__ bias, float* __restrict__ sOut,
    bool relu, int tid)
{
    const int rt = tid >> 5;
    const int l  = tid & 31;

    float4 acc[4];
    #pragma unroll
    for (int r = 0; r < 4; ++r) acc[r] = make_float4(0.f, 0.f, 0.f, 0.f);

    const float* wp = W + 4 * l;
    #pragma unroll 4
    for (int k = 0; k < 128; ++k) {
        float4 w = *reinterpret_cast<const float4*>(wp + (size_t)k * 128);
        #pragma unroll
        for (int r = 0; r < 4; ++r) {
            float a = sIn[(rt * 4 + r) * 128 + k];   // warp-uniform -> LDS broadcast
            acc[r].x = fmaf(a, w.x, acc[r].x);
            acc[r].y = fmaf(a, w.y, acc[r].y);
            acc[r].z = fmaf(a, w.z, acc[r].z);
            acc[r].w = fmaf(a, w.w, acc[r].w);
        }
    }

    float4 bv = *reinterpret_cast<const float4*>(bias + 4 * l);
    #pragma unroll
    for (int r = 0; r < 4; ++r) {
        float4 o = acc[r];
        o.x += bv.x; o.y += bv.y; o.z += bv.z; o.w += bv.w;
        if (relu) {
            o.x = fmaxf(o.x, 0.f); o.y = fmaxf(o.y, 0.f);
            o.z = fmaxf(o.z, 0.f); o.w = fmaxf(o.w, 0.f);
        }
        *reinterpret_cast<float4*>(sOut + (rt * 4 + r) * 128 + 4 * l) = o;
    }
}

// ---------------------------------------------------------------------------
// Kernel 2: fused per-point attention. One block per point (b,n), 128 threads.
//   pos_enc (2 layers) -> rel -> attn MLP (2 layers) -> per-channel softmax
//   over K -> aggregate -> output projection Wo.
// ---------------------------------------------------------------------------
__global__ void __launch_bounds__(128) attn_kernel(
    const float* __restrict__ pos, const int* __restrict__ idx,
    const float* __restrict__ Wp1, const float* __restrict__ bp1,
    const float* __restrict__ Wp2, const float* __restrict__ bp2,
    const float* __restrict__ Wa1, const float* __restrict__ ba1,
    const float* __restrict__ Wa2, const float* __restrict__ ba2,
    const float* __restrict__ Wo,  const float* __restrict__ bo,
    float* __restrict__ out)
{
    __shared__ float sA[16 * 128];   // hidden, then mid
    __shared__ float sB[16 * 128];   // pos_enc
    __shared__ float sC[16 * 128];   // rel, then logits
    __shared__ float s_q[128];
    __shared__ float s_agg[128];
    __shared__ float s_pd[16][3];
    __shared__ int   s_idx[16];

    const int tid = threadIdx.x;
    const int p   = blockIdx.x;            // global point id
    const int b   = p / NN;
    const size_t pbase = (size_t)p * COUT;
    const size_t bbase = (size_t)b * NN;

    if (tid < KK) s_idx[tid] = idx[(size_t)p * KK + tid];
    s_q[tid] = g_q[pbase + tid];
    __syncthreads();

    if (tid < KK * 3) {
        int k = tid / 3, i = tid % 3;
        float pc = pos[(size_t)p * 3 + i];
        float pn = pos[(bbase + (size_t)s_idx[k]) * 3 + i];
        s_pd[k][i] = pc - pn;
    }
    __syncthreads();

    // stage 1: hidden = relu(pos_diff @ Wp1 + bp1)   (K=3, elementwise-cheap)
    for (int e = tid; e < KK * 128; e += 128) {
        int k = e >> 7, c = e & 127;
        float h = fmaf(s_pd[k][0], Wp1[c],
                  fmaf(s_pd[k][1], Wp1[128 + c],
                  fmaf(s_pd[k][2], Wp1[256 + c], bp1[c])));
        sA[e] = fmaxf(h, 0.f);
    }
    __syncthreads();

    // stage 2: pos_enc = hidden @ Wp2 + bp2
    gemm16x128(sA, Wp2, bp2, sB, false, tid);
    __syncthreads();

    // stage 3: rel = k_n - q + pos_enc
    for (int e = tid; e < KK * 128; e += 128) {
        int k = e >> 7, c = e & 127;
        float kn = g_k[(bbase + (size_t)s_idx[k]) * COUT + c];
        sC[e] = kn - s_q[c] + sB[e];
    }
    __syncthreads();

    // stage 4: mid = relu(rel @ Wa1 + ba1)
    gemm16x128(sC, Wa1, ba1, sA, true, tid);
    __syncthreads();

    // stage 5: logits = mid @ Wa2 + ba2
    gemm16x128(sA, Wa2, ba2, sC, false, tid);
    __syncthreads();

    // stage 6: per-channel softmax over K + aggregate with (v_n + pos_enc)
    {
        const int c = tid;
        float m = -1e30f;
        #pragma unroll
        for (int k = 0; k < KK; ++k) m = fmaxf(m, sC[k * 128 + c]);
        float ex[KK];
        float s = 0.f;
        #pragma unroll
        for (int k = 0; k < KK; ++k) {
            float e_ = __expf(sC[k * 128 + c] - m);
            ex[k] = e_;
            s += e_;
        }
        float inv = 1.f / s;
        float agg = 0.f;
        #pragma unroll
        for (int k = 0; k < KK; ++k) {
            float v = g_v[(bbase + (size_t)s_idx[k]) * COUT + c];
            agg = fmaf(ex[k], v + sB[k * 128 + c], agg);
        }
        s_agg[c] = agg * inv;
    }
    __syncthreads();

    // stage 7: out = agg @ Wo + bo (GEMV, weights L1-hot, coalesced per warp)
    {
        const int c = tid;
        float acc = bo[c];
        #pragma unroll 8
        for (int k = 0; k < 128; ++k)
            acc = fmaf(s_agg[k], Wo[(size_t)k * 128 + c], acc);
        out[pbase + c] = acc;
    }
}

// ---------------------------------------------------------------------------
extern "C" void kernel_launch(void* const* d_in, const int* in_sizes, int n_in,
                              void* d_out, int out_size)
{
    const float* x   = (const float*)d_in[0];
    const float* pos = (const float*)d_in[1];
    const int*   idx = (const int*)  d_in[2];
    const float* Wq  = (const float*)d_in[3];
    const float* bq  = (const float*)d_in[4];
    const float* Wkv = (const float*)d_in[5];
    const float* bkv = (const float*)d_in[6];
    const float* Wp1 = (const float*)d_in[7];
    const float* bp1 = (const float*)d_in[8];
    const float* Wp2 = (const float*)d_in[9];
    const float* bp2 = (const float*)d_in[10];
    const float* Wa1 = (const float*)d_in[11];
    const float* ba1 = (const float*)d_in[12];
    const float* Wa2 = (const float*)d_in[13];
    const float* ba2 = (const float*)d_in[14];
    const float* Wo  = (const float*)d_in[15];
    const float* bo  = (const float*)d_in[16];
    float* out = (float*)d_out;

    dim3 g1(NPTS / 16, 3);
    proj_kernel<<<g1, 128>>>(x, Wq, bq, Wkv, bkv);
    attn_kernel<<<NPTS, 128>>>(pos, idx, Wp1, bp1, Wp2, bp2,
                               Wa1, ba1, Wa2, ba2, Wo, bo, out);
}

// round 6
// speedup vs baseline: 1.2151x; 1.2151x over previous
#include <cuda_runtime.h>

#define BB   2
#define NN   8192
#define KK   16
#define CIN  64
#define COUT 128
#define NPTS (BB * NN)

// Scratch for projected q/k/v + repacked weights (device globals: no allocation allowed)
__device__ float g_q[NPTS * COUT];
__device__ float g_k[NPTS * COUT];
__device__ float g_v[NPTS * COUT];
__device__ __align__(16) float g_Wp2r[COUT * COUT];
__device__ __align__(16) float g_Wa1r[COUT * COUT];
__device__ __align__(16) float g_Wa2r[COUT * COUT];

// packed fp32x2 FMA: acc.xy += a.xy * w.xy  (sm_100+ only; not emitted by nvcc from C++)
__device__ __forceinline__ void fma2(unsigned long long& acc,
                                     unsigned long long a, unsigned long long w) {
    asm("fma.rn.f32x2 %0, %1, %2, %0;" : "+l"(acc) : "l"(a), "l"(w));
}

// ---------------------------------------------------------------------------
// Kernel 0: repack W[k][c] (128x128) -> Wr[(k/4)*128 + c] float4 = W[4kq..4kq+3][c]
// ---------------------------------------------------------------------------
__global__ void __launch_bounds__(256) repack_kernel(
    const float* __restrict__ Wp2, const float* __restrict__ Wa1,
    const float* __restrict__ Wa2)
{
    int i = blockIdx.x * 256 + threadIdx.x;   // 0..16383
    int g = blockIdx.y;
    const float* W = (g == 0) ? Wp2 : (g == 1) ? Wa1 : Wa2;
    float*      Wr = (g == 0) ? g_Wp2r : (g == 1) ? g_Wa1r : g_Wa2r;
    int k = i >> 7, c = i & 127;
    Wr[((k >> 2) * 128 + c) * 4 + (k & 3)] = W[i];
}

// ---------------------------------------------------------------------------
// Kernel 1: q = x@Wq+bq ; k,v = x@Wkv+bkv  (16 rows x 128 cols per block)
// ---------------------------------------------------------------------------
__global__ void __launch_bounds__(128) proj_kernel(
    const float* __restrict__ x,
    const float* __restrict__ Wq,  const float* __restrict__ bq,
    const float* __restrict__ Wkv, const float* __restrict__ bkv)
{
    __shared__ float s_x[16][64];

    const int tid  = threadIdx.x;
    const int row0 = blockIdx.x * 16;
    const int g    = blockIdx.y;

    for (int i = tid; i < 256; i += 128) {
        int r = i >> 4, c4 = i & 15;
        reinterpret_cast<float4*>(&s_x[r][0])[c4] =
            reinterpret_cast<const float4*>(x + (size_t)(row0 + r) * CIN)[c4];
    }
    __syncthreads();

    const int rt = tid >> 5;
    const int l  = tid & 31;

    const float* W; const float* bias; float* out;
    int ldw, cb;
    if (g == 0)      { W = Wq;  ldw = 128; cb = 0;   bias = bq;        out = g_q; }
    else if (g == 1) { W = Wkv; ldw = 256; cb = 0;   bias = bkv;       out = g_k; }
    else             { W = Wkv; ldw = 256; cb = 128; bias = bkv + 128; out = g_v; }

    float4 acc[4];
    #pragma unroll
    for (int r = 0; r < 4; ++r) acc[r] = make_float4(0.f, 0.f, 0.f, 0.f);

    const float* wp = W + cb + 4 * l;
    #pragma unroll 4
    for (int k = 0; k < CIN; ++k) {
        float4 w = *reinterpret_cast<const float4*>(wp + (size_t)k * ldw);
        #pragma unroll
        for (int r = 0; r < 4; ++r) {
            float a = s_x[rt * 4 + r][k];
            acc[r].x = fmaf(a, w.x, acc[r].x);
            acc[r].y = fmaf(a, w.y, acc[r].y);
            acc[r].z = fmaf(a, w.z, acc[r].z);
            acc[r].w = fmaf(a, w.w, acc[r].w);
        }
    }

    float4 bv = *reinterpret_cast<const float4*>(bias + 4 * l);
    #pragma unroll
    for (int r = 0; r < 4; ++r) {
        float4 o = acc[r];
        o.x += bv.x; o.y += bv.y; o.z += bv.z; o.w += bv.w;
        *reinterpret_cast<float4*>(out + (size_t)(row0 + rt * 4 + r) * COUT + 4 * l) = o;
    }
}

// ---------------------------------------------------------------------------
// Packed-f32x2 GEMM stage: 32x128 (smem, row-major) @ 128x128 (repacked gmem).
// 256 threads: warp w owns rows w*4..w*4+3; lane l owns cols l, l+32, l+64, l+96.
// k paired: acc holds (even-of-pair, odd-of-pair) partial sums, added at end.
// Safe in-place (sIn == sOut): each warp reads only its own rows, writes after.
// ---------------------------------------------------------------------------
__device__ __forceinline__ void gemm32x128_f32x2(
    const float* __restrict__ sIn, const float* __restrict__ Wr,
    const float* __restrict__ bias, float* __restrict__ sOut,
    bool relu, int wid, int l)
{
    const int r0 = wid * 4;
    unsigned long long acc[4][4];
    #pragma unroll
    for (int r = 0; r < 4; ++r)
        #pragma unroll
        for (int m = 0; m < 4; ++m) acc[r][m] = 0ull;

    const ulonglong2* __restrict__ W2 = reinterpret_cast<const ulonglong2*>(Wr);

    #pragma unroll 2
    for (int kq = 0; kq < 32; ++kq) {         // 4 k-values per iteration
        ulonglong2 a[4];
        #pragma unroll
        for (int r = 0; r < 4; ++r)
            a[r] = *reinterpret_cast<const ulonglong2*>(&sIn[(r0 + r) * 128 + kq * 4]);
        #pragma unroll
        for (int m = 0; m < 4; ++m) {
            ulonglong2 w = W2[kq * 128 + (l + 32 * m)];
            #pragma unroll
            for (int r = 0; r < 4; ++r) {
                fma2(acc[r][m], a[r].x, w.x);
                fma2(acc[r][m], a[r].y, w.y);
            }
        }
    }

    float bv[4];
    #pragma unroll
    for (int m = 0; m < 4; ++m) bv[m] = bias[l + 32 * m];

    #pragma unroll
    for (int r = 0; r < 4; ++r)
        #pragma unroll
        for (int m = 0; m < 4; ++m) {
            unsigned long long u = acc[r][m];
            float v = __uint_as_float((unsigned)u) +
                      __uint_as_float((unsigned)(u >> 32)) + bv[m];
            if (relu) v = fmaxf(v, 0.f);
            sOut[(r0 + r) * 128 + (l + 32 * m)] = v;
        }
}

// ---------------------------------------------------------------------------
// Kernel 2: fused attention, 2 points per CTA, 256 threads.
// ---------------------------------------------------------------------------
__global__ void __launch_bounds__(256) attn_kernel(
    const float* __restrict__ pos, const int* __restrict__ idx,
    const float* __restrict__ Wp1, const float* __restrict__ bp1,
    const float* __restrict__ bp2,
    const float* __restrict__ ba1,
    const float* __restrict__ ba2,
    const float* __restrict__ Wo,  const float* __restrict__ bo,
    float* __restrict__ out)
{
    __shared__ __align__(16) float sA[32 * 128];   // hidden -> rel -> mid -> logits
    __shared__ __align__(16) float sB[32 * 128];   // pos_enc (persists)
    __shared__ __align__(16) float s_q[256];
    __shared__ float s_agg[256];
    __shared__ float s_pd[32][3];
    __shared__ int   s_idx[32];

    const int tid = threadIdx.x;
    const int wid = tid >> 5;
    const int l   = tid & 31;
    const int p0  = blockIdx.x * 2;                 // first point (p0, p0+1 same batch)
    const int b   = p0 / NN;
    const int bbase = b * NN;

    if (tid < 32) s_idx[tid] = idx[p0 * KK + tid];  // 2 points' neighbors, contiguous
    s_q[tid] = g_q[p0 * COUT + tid];
    __syncthreads();

    if (tid < 32 * 3) {
        int r = tid / 3, i = tid % 3;
        int pi = r >> 4;
        float pc = pos[(p0 + pi) * 3 + i];
        float pn = pos[(bbase + s_idx[r]) * 3 + i];
        s_pd[r][i] = pc - pn;
    }
    __syncthreads();

    // stage 1: hidden = relu(pos_diff @ Wp1 + bp1)   (c fixed per thread)
    {
        const int c = tid & 127;
        float w0 = Wp1[c], w1 = Wp1[128 + c], w2 = Wp1[256 + c], bb = bp1[c];
        #pragma unroll
        for (int j = 0; j < 16; ++j) {
            int r = (tid >> 7) + 2 * j;
            float h = fmaf(s_pd[r][0], w0, fmaf(s_pd[r][1], w1, fmaf(s_pd[r][2], w2, bb)));
            sA[r * 128 + c] = fmaxf(h, 0.f);
        }
    }
    __syncthreads();

    // stage 2: pos_enc = hidden @ Wp2 + bp2
    gemm32x128_f32x2(sA, g_Wp2r, bp2, sB, false, wid, l);
    __syncthreads();

    // stage 3: rel = k_n - q + pos_enc   (float4, coalesced gather)
    for (int e = tid; e < 32 * 32; e += 256) {
        int r = e >> 5, c4 = e & 31;
        int pi = r >> 4;
        float4 kn = *reinterpret_cast<const float4*>(
            &g_k[(size_t)(bbase + s_idx[r]) * COUT + 4 * c4]);
        float4 q4 = *reinterpret_cast<const float4*>(&s_q[pi * 128 + 4 * c4]);
        float4 pe = *reinterpret_cast<const float4*>(&sB[r * 128 + 4 * c4]);
        float4 o;
        o.x = kn.x - q4.x + pe.x; o.y = kn.y - q4.y + pe.y;
        o.z = kn.z - q4.z + pe.z; o.w = kn.w - q4.w + pe.w;
        *reinterpret_cast<float4*>(&sA[r * 128 + 4 * c4]) = o;
    }
    __syncthreads();

    // stage 4: mid = relu(rel @ Wa1 + ba1)   (in place)
    gemm32x128_f32x2(sA, g_Wa1r, ba1, sA, true, wid, l);
    __syncthreads();

    // stage 5: logits = mid @ Wa2 + ba2      (in place)
    gemm32x128_f32x2(sA, g_Wa2r, ba2, sA, false, wid, l);
    __syncthreads();

    // stage 6: per-channel softmax over K + aggregate with (v_n + pos_enc)
    {
        const int pi = tid >> 7, c = tid & 127;
        const float* lg = &sA[pi * 16 * 128 + c];
        const float* pe = &sB[pi * 16 * 128 + c];
        float m = -1e30f;
        #pragma unroll
        for (int k = 0; k < KK; ++k) m = fmaxf(m, lg[k * 128]);
        float ex[KK]; float s = 0.f;
        #pragma unroll
        for (int k = 0; k < KK; ++k) { float e_ = __expf(lg[k * 128] - m); ex[k] = e_; s += e_; }
        float inv = 1.f / s;
        float agg = 0.f;
        #pragma unroll
        for (int k = 0; k < KK; ++k) {
            float v = g_v[(size_t)(bbase + s_idx[pi * 16 + k]) * COUT + c];
            agg = fmaf(ex[k], v + pe[k * 128], agg);
        }
        s_agg[tid] = agg * inv;
    }
    __syncthreads();

    // stage 7: out = agg @ Wo + bo  (2-point GEMV, Wo rows L1-hot)
    {
        const int pi = tid >> 7, c = tid & 127;
        float acc = bo[c];
        const float* ag = &s_agg[pi * 128];
        #pragma unroll 8
        for (int k = 0; k < 128; ++k)
            acc = fmaf(ag[k], Wo[(size_t)k * 128 + c], acc);
        out[(size_t)(p0 + pi) * COUT + c] = acc;
    }
}

// ---------------------------------------------------------------------------
extern "C" void kernel_launch(void* const* d_in, const int* in_sizes, int n_in,
                              void* d_out, int out_size)
{
    const float* x   = (const float*)d_in[0];
    const float* pos = (const float*)d_in[1];
    const int*   idx = (const int*)  d_in[2];
    const float* Wq  = (const float*)d_in[3];
    const float* bq  = (const float*)d_in[4];
    const float* Wkv = (const float*)d_in[5];
    const float* bkv = (const float*)d_in[6];
    const float* Wp1 = (const float*)d_in[7];
    const float* bp1 = (const float*)d_in[8];
    const float* Wp2 = (const float*)d_in[9];
    const float* bp2 = (const float*)d_in[10];
    const float* Wa1 = (const float*)d_in[11];
    const float* ba1 = (const float*)d_in[12];
    const float* Wa2 = (const float*)d_in[13];
    const float* ba2 = (const float*)d_in[14];
    const float* Wo  = (const float*)d_in[15];
    const float* bo  = (const float*)d_in[16];
    float* out = (float*)d_out;

    dim3 gr(64, 3);
    repack_kernel<<<gr, 256>>>(Wp2, Wa1, Wa2);
    dim3 g1(NPTS / 16, 3);
    proj_kernel<<<g1, 128>>>(x, Wq, bq, Wkv, bkv);
    attn_kernel<<<NPTS / 2, 256>>>(pos, idx, Wp1, bp1, bp2, ba1, ba2, Wo, bo, out);
}